// round 4
// baseline (speedup 1.0000x reference)
#include <cuda_runtime.h>

#define T_FRAMES 32768
#define N_LM 543
#define NLEN 512
#define NCOLS 122   // 21*2 hand + 40*2 lips
#define NHANDF 42
#define NLIPSF 80
#define FPB 8       // frames per block in k_frame (256 threads)
#define RAWS 128    // padded row stride of g_raw (floats) -> 512B aligned rows
#define NBLK (T_FRAMES / FPB)

// ---- device scratch (static; no allocations) ----
__device__ __align__(128) float g_raw[T_FRAMES * RAWS];
__device__ __align__(128) unsigned char g_keep8[NBLK];   // 1 bit per frame
__device__ __align__(128) int   g_map[T_FRAMES];
__device__ float g_lsum[NLIPSF];
__device__ int   g_lcnt[NLIPSF];
__device__ float g_lmean[NLIPSF];
__device__ int   g_S;
__device__ __align__(128) float g_sampled[NLEN * NCOLS];
__device__ int   g_rowflag[NLEN];

__device__ __forceinline__ bool is_nan(float v) { return v != v; }

// ---- kernel 0: zero accumulators (must run every replay) ----
__global__ void k_init() {
    int i = threadIdx.x;
    if (i < NLIPSF) { g_lsum[i] = 0.f; g_lcnt[i] = 0; }
}

// ---- kernel 1: per-frame hand transform + keep bit + raw buffer + lips accum ----
__global__ void k_frame(const float* __restrict__ frames, const int* __restrict__ lips_idx) {
    __shared__ int   s_lidx[40];
    __shared__ float s_lips[FPB][NLIPSF];
    __shared__ int   s_keepw[FPB];

    int tib  = threadIdx.x;
    int lane = tib & 31;
    int w    = tib >> 5;
    int t    = blockIdx.x * FPB + w;
    const float NANF = __int_as_float(0x7fc00000);

    if (tib < 40) s_lidx[tib] = lips_idx[tib];
    __syncthreads();

    const float* fb = frames + (size_t)t * (N_LM * 3);

    int nz = 0;
    if (lane < 21) {
        float lx = __ldg(&fb[(468 + lane) * 3 + 0]);
        float ly = __ldg(&fb[(468 + lane) * 3 + 1]);
        float rx = __ldg(&fb[(522 + lane) * 3 + 0]);
        float ry = __ldg(&fb[(522 + lane) * 3 + 1]);
        float a0 = is_nan(lx) ? 0.f : lx;
        float a1 = is_nan(ly) ? 0.f : (1.f - ly);
        float b0 = is_nan(rx) ? 0.f : (1.f - rx);
        float b1 = is_nan(ry) ? 0.f : (1.f - ry);
        float h0 = a0 + b0;
        float h1 = a1 + b1;
        g_raw[t * RAWS + 2 * lane + 0] = h0;
        g_raw[t * RAWS + 2 * lane + 1] = h1;
        nz = (h0 != 0.f) | (h1 != 0.f);   // terms are non-negative => sum!=0 <=> any!=0
    }
    unsigned bal = __ballot_sync(0xffffffffu, nz);
    int keep = (bal != 0u);
    if (lane == 0) s_keepw[w] = keep;

    // lips gather; stash (value-if-kept-else-NaN) in shared for block reduction
    #pragma unroll
    for (int j = lane; j < 40; j += 32) {
        int li  = s_lidx[j];
        float x = __ldg(&fb[li * 3 + 0]);
        float y = __ldg(&fb[li * 3 + 1]);
        g_raw[t * RAWS + NHANDF + 2 * j + 0] = x;
        g_raw[t * RAWS + NHANDF + 2 * j + 1] = y;
        s_lips[w][2 * j + 0] = keep ? x : NANF;
        s_lips[w][2 * j + 1] = keep ? y : NANF;
    }
    __syncthreads();

    if (tib == 0) {
        unsigned m = 0;
        #pragma unroll
        for (int f = 0; f < FPB; f++) m |= (unsigned)s_keepw[f] << f;
        g_keep8[blockIdx.x] = (unsigned char)m;
    }

    // 80 threads: reduce FPB frames for one column, single global atomic pair
    if (tib < NLIPSF) {
        float s = 0.f; int c = 0;
        #pragma unroll
        for (int f = 0; f < FPB; f++) {
            float v = s_lips[f][tib];
            if (!is_nan(v)) { s += v; c++; }
        }
        if (c) {
            atomicAdd(&g_lsum[tib], s);
            atomicAdd(&g_lcnt[tib], c);
        }
    }
}

// ---- kernel 2: ballot-based compaction of keep bits -> g_map + S; lips means ----
__global__ void k_scan() {
    int tid  = threadIdx.x;   // 1024 threads = 32 warps
    int lane = tid & 31;
    int w    = tid >> 5;

    if (tid < NLIPSF) {
        int c = g_lcnt[tid];
        g_lmean[tid] = (c > 0) ? g_lsum[tid] / (float)c : 0.f;
    }

    __shared__ unsigned s_ball[1024];  // [warp][k]
    __shared__ int s_cnt[32];
    __shared__ int s_off[32];

    int t0  = w * 1024;
    int cnt = 0;
    #pragma unroll
    for (int k = 0; k < 32; k++) {
        int t  = t0 + k * 32 + lane;
        int kp = (g_keep8[t >> 3] >> (t & 7)) & 1;
        unsigned b = __ballot_sync(0xffffffffu, kp);
        if (lane == 0) s_ball[w * 32 + k] = b;
        cnt += __popc(b);
    }
    if (lane == 0) s_cnt[w] = cnt;
    __syncthreads();
    if (tid == 0) {
        int acc = 0;
        #pragma unroll
        for (int i = 0; i < 32; i++) { s_off[i] = acc; acc += s_cnt[i]; }
        g_S = acc;
    }
    __syncthreads();

    int off = s_off[w];
    #pragma unroll
    for (int k = 0; k < 32; k++) {
        unsigned b = s_ball[w * 32 + k];
        int t = t0 + k * 32 + lane;
        if ((b >> lane) & 1)
            g_map[off + __popc(b & ((1u << lane) - 1u))] = t;
        off += __popc(b);
    }
}

// ---- kernel 3: segment means (512 blocks x 512 thr = 128 cols x 4 slices) ----
__global__ void k_segment() {
    int i = blockIdx.x;
    int S = g_S;
    int lo = 0, hi = 0;
    if (S >= 2) {
        long sm1 = (long)(S - 1);
        lo = (int)(((long)i       * sm1) >> 9);   // floor(i*(S-1)/512)
        hi = (int)(((long)(i + 1) * sm1) >> 9);
    }
    int cnt = hi - lo;   // <= 64

    __shared__ int   s_map[66];
    __shared__ float red[4][128];

    if (threadIdx.x < cnt) s_map[threadIdx.x] = g_map[lo + threadIdx.x];
    __syncthreads();

    int j     = threadIdx.x & 127;
    int slice = threadIdx.x >> 7;

    float sum = 0.f;
    if (j < NCOLS) {
        float fill = (j >= NHANDF) ? g_lmean[j - NHANDF] : 0.f;
        #pragma unroll 2
        for (int s = slice; s < cnt; s += 4) {
            int t = s_map[s];
            float v = g_raw[t * RAWS + j];
            sum += is_nan(v) ? fill : v;
        }
    }
    red[slice][j] = sum;
    __syncthreads();

    float mean = 0.f;
    if (slice == 0) {
        float total = red[0][j] + red[1][j] + red[2][j] + red[3][j];
        if (j < NCOLS) {
            mean = cnt ? total / (float)cnt : 0.f;
            g_sampled[i * NCOLS + j] = mean;
        }
    }
    __syncthreads();
    if (slice == 0) red[0][j] = mean;
    __syncthreads();
    if (threadIdx.x < 32) {
        float r = red[0][threadIdx.x] + red[0][threadIdx.x + 32]
                + red[0][threadIdx.x + 64] + red[0][threadIdx.x + 96];
        #pragma unroll
        for (int off = 16; off; off >>= 1)
            r += __shfl_xor_sync(0xffffffffu, r, off);
        if (threadIdx.x == 0) g_rowflag[i] = (r != 0.f);
    }
}

// ---- kernel 4: row compaction into d_out ----
__global__ void k_compact(float* __restrict__ out, int out_size) {
    __shared__ int sflag[NLEN];
    __shared__ int ssrc[NLEN];
    int tid = threadIdx.x;   // 512 threads
    int f = g_rowflag[tid];
    sflag[tid] = f;
    __syncthreads();
    for (int off = 1; off < NLEN; off <<= 1) {
        int v = (tid >= off) ? sflag[tid - off] : 0;
        __syncthreads();
        sflag[tid] += v;
        __syncthreads();
    }
    if (f) ssrc[sflag[tid] - 1] = tid;
    __syncthreads();
    int R = sflag[NLEN - 1];
    int total = R * NCOLS;
    if (total > out_size) total = out_size;
    for (int k = tid; k < total; k += NLEN) {
        int r = k / NCOLS;
        int c = k - r * NCOLS;
        out[k] = g_sampled[ssrc[r] * NCOLS + c];
    }
}

extern "C" void kernel_launch(void* const* d_in, const int* in_sizes, int n_in,
                              void* d_out, int out_size) {
    const float* frames   = (const float*)d_in[0];
    const int*   lips_idx = (const int*)d_in[1];
    float*       out      = (float*)d_out;

    k_init<<<1, 128>>>();
    k_frame<<<NBLK, FPB * 32>>>(frames, lips_idx);
    k_scan<<<1, 1024>>>();
    k_segment<<<NLEN, 512>>>();
    k_compact<<<1, NLEN>>>(out, out_size);
}

// round 5
// speedup vs baseline: 1.0615x; 1.0615x over previous
#include <cuda_runtime.h>

#define T_FRAMES 32768
#define N_LM 543
#define NLEN 512
#define NCOLS 122   // 21*2 hand + 40*2 lips
#define NHANDF 42
#define NLIPSF 80
#define FPB 8       // frames per block in k_frame (256 threads)
#define RAWS 128    // padded row stride of g_raw (floats) -> 512B aligned rows
#define NBLK (T_FRAMES / FPB)

// ---- device scratch (static; no allocations) ----
__device__ __align__(128) float g_raw[T_FRAMES * RAWS];
__device__ __align__(128) unsigned char g_keep8[NBLK];   // 1 bit per frame
__device__ __align__(128) int   g_map[T_FRAMES];
__device__ float g_lsum[NLIPSF];   // zero at entry of every kernel_launch (re-zeroed by k_scan)
__device__ int   g_lcnt[NLIPSF];
__device__ float g_lmean[NLIPSF];
__device__ int   g_S;
__device__ __align__(128) float g_sampled[NLEN * NCOLS];
__device__ int   g_rowflag[NLEN];

__device__ __forceinline__ bool is_nan(float v) { return v != v; }

// ---- kernel 1: per-frame hand transform + keep bit + raw buffer + lips accum ----
// All 8 loads per thread issued up-front (single memory phase); keep gates stores only.
__global__ void k_frame(const float* __restrict__ frames, const int* __restrict__ lips_idx) {
    __shared__ int   s_lidx[40];
    __shared__ float s_lips[FPB][NLIPSF];
    __shared__ int   s_keepw[FPB];

    int tib  = threadIdx.x;
    int lane = tib & 31;
    int w    = tib >> 5;
    int t    = blockIdx.x * FPB + w;
    const float NANF = __int_as_float(0x7fc00000);

    if (tib < 40) s_lidx[tib] = lips_idx[tib];
    __syncthreads();

    const float* fb = frames + (size_t)t * (N_LM * 3);

    // ---- batched loads (all independent, issued before any consumption) ----
    float lx = NANF, ly = NANF, rx = NANF, ry = NANF;
    if (lane < 21) {
        lx = __ldg(fb + (468 + lane) * 3 + 0);
        ly = __ldg(fb + (468 + lane) * 3 + 1);
        rx = __ldg(fb + (522 + lane) * 3 + 0);
        ry = __ldg(fb + (522 + lane) * 3 + 1);
    }
    int   li0 = s_lidx[lane];
    float x0  = __ldg(fb + li0 * 3 + 0);
    float y0  = __ldg(fb + li0 * 3 + 1);
    float x1 = NANF, y1 = NANF;
    if (lane < 8) {
        int li1 = s_lidx[32 + lane];
        x1 = __ldg(fb + li1 * 3 + 0);
        y1 = __ldg(fb + li1 * 3 + 1);
    }

    // ---- hand transform + keep ----
    float a0 = is_nan(lx) ? 0.f : lx;
    float a1 = is_nan(ly) ? 0.f : (1.f - ly);
    float b0 = is_nan(rx) ? 0.f : (1.f - rx);
    float b1 = is_nan(ry) ? 0.f : (1.f - ry);
    float h0 = a0 + b0;
    float h1 = a1 + b1;
    int nz = (lane < 21) && ((h0 != 0.f) | (h1 != 0.f));  // terms non-negative => sum!=0 <=> any!=0
    unsigned bal = __ballot_sync(0xffffffffu, nz);
    int keep = (bal != 0u);
    if (lane == 0) s_keepw[w] = keep;

    // ---- stores (only kept frames are ever read back) ----
    float* row = &g_raw[t * RAWS];
    if (keep) {
        if (lane < 21) *(float2*)(row + 2 * lane) = make_float2(h0, h1);
        *(float2*)(row + NHANDF + 2 * lane) = make_float2(x0, y0);
        if (lane < 8) *(float2*)(row + NHANDF + 64 + 2 * lane) = make_float2(x1, y1);
    }

    // lips stash for block-level mean accumulation (NaN if frame not kept)
    s_lips[w][2 * lane + 0] = keep ? x0 : NANF;
    s_lips[w][2 * lane + 1] = keep ? y0 : NANF;
    if (lane < 8) {
        s_lips[w][64 + 2 * lane + 0] = keep ? x1 : NANF;
        s_lips[w][64 + 2 * lane + 1] = keep ? y1 : NANF;
    }
    __syncthreads();

    if (tib == 0) {
        unsigned m = 0;
        #pragma unroll
        for (int f = 0; f < FPB; f++) m |= (unsigned)s_keepw[f] << f;
        g_keep8[blockIdx.x] = (unsigned char)m;
    }

    // 80 threads: reduce FPB frames for one column, single global atomic pair
    if (tib < NLIPSF) {
        float s = 0.f; int c = 0;
        #pragma unroll
        for (int f = 0; f < FPB; f++) {
            float v = s_lips[f][tib];
            if (!is_nan(v)) { s += v; c++; }
        }
        if (c) {
            atomicAdd(&g_lsum[tib], s);
            atomicAdd(&g_lcnt[tib], c);
        }
    }
}

// ---- kernel 2: ballot-based compaction -> g_map + S; lips means; re-zero accumulators ----
__global__ void k_scan() {
    int tid  = threadIdx.x;   // 1024 threads = 32 warps
    int lane = tid & 31;
    int w    = tid >> 5;

    if (tid < NLIPSF) {
        int c = g_lcnt[tid];
        g_lmean[tid] = (c > 0) ? g_lsum[tid] / (float)c : 0.f;
        g_lsum[tid] = 0.f;     // restore zero-at-entry invariant for next launch
        g_lcnt[tid] = 0;
    }

    __shared__ unsigned s_ball[1024];  // [warp][k]
    __shared__ int s_cnt[32];
    __shared__ int s_off[32];

    int t0  = w * 1024;
    int cnt = 0;
    #pragma unroll
    for (int k = 0; k < 32; k++) {
        int t  = t0 + k * 32 + lane;
        int kp = (g_keep8[t >> 3] >> (t & 7)) & 1;
        unsigned b = __ballot_sync(0xffffffffu, kp);
        if (lane == 0) s_ball[w * 32 + k] = b;
        cnt += __popc(b);
    }
    if (lane == 0) s_cnt[w] = cnt;
    __syncthreads();
    if (tid == 0) {
        int acc = 0;
        #pragma unroll
        for (int i = 0; i < 32; i++) { s_off[i] = acc; acc += s_cnt[i]; }
        g_S = acc;
    }
    __syncthreads();

    int off = s_off[w];
    #pragma unroll
    for (int k = 0; k < 32; k++) {
        unsigned b = s_ball[w * 32 + k];
        int t = t0 + k * 32 + lane;
        if ((b >> lane) & 1)
            g_map[off + __popc(b & ((1u << lane) - 1u))] = t;
        off += __popc(b);
    }
}

// ---- kernel 3: segment means (512 blocks x 512 thr = 128 cols x 4 slices) ----
__global__ void k_segment() {
    int i = blockIdx.x;
    int S = g_S;
    int lo = 0, hi = 0;
    if (S >= 2) {
        long sm1 = (long)(S - 1);
        lo = (int)(((long)i       * sm1) >> 9);   // floor(i*(S-1)/512)
        hi = (int)(((long)(i + 1) * sm1) >> 9);
    }
    int cnt = hi - lo;   // <= 64

    __shared__ int   s_map[66];
    __shared__ float red[4][128];

    if (threadIdx.x < cnt) s_map[threadIdx.x] = g_map[lo + threadIdx.x];
    __syncthreads();

    int j     = threadIdx.x & 127;
    int slice = threadIdx.x >> 7;

    float sum = 0.f;
    if (j < NCOLS) {
        float fill = (j >= NHANDF) ? g_lmean[j - NHANDF] : 0.f;
        #pragma unroll 4
        for (int s = slice; s < cnt; s += 4) {
            int t = s_map[s];
            float v = g_raw[t * RAWS + j];
            sum += is_nan(v) ? fill : v;
        }
    }
    red[slice][j] = sum;
    __syncthreads();

    float mean = 0.f;
    if (slice == 0) {
        float total = red[0][j] + red[1][j] + red[2][j] + red[3][j];
        if (j < NCOLS) {
            mean = cnt ? total / (float)cnt : 0.f;
            g_sampled[i * NCOLS + j] = mean;
        }
    }
    __syncthreads();
    if (slice == 0) red[0][j] = mean;
    __syncthreads();
    if (threadIdx.x < 32) {
        float r = red[0][threadIdx.x] + red[0][threadIdx.x + 32]
                + red[0][threadIdx.x + 64] + red[0][threadIdx.x + 96];
        #pragma unroll
        for (int off = 16; off; off >>= 1)
            r += __shfl_xor_sync(0xffffffffu, r, off);
        if (threadIdx.x == 0) g_rowflag[i] = (r != 0.f);
    }
}

// ---- kernel 4: row compaction into d_out ----
__global__ void k_compact(float* __restrict__ out, int out_size) {
    __shared__ int sflag[NLEN];
    __shared__ int ssrc[NLEN];
    int tid = threadIdx.x;   // 512 threads
    int f = g_rowflag[tid];
    sflag[tid] = f;
    __syncthreads();
    for (int off = 1; off < NLEN; off <<= 1) {
        int v = (tid >= off) ? sflag[tid - off] : 0;
        __syncthreads();
        sflag[tid] += v;
        __syncthreads();
    }
    if (f) ssrc[sflag[tid] - 1] = tid;
    __syncthreads();
    int R = sflag[NLEN - 1];
    int total = R * NCOLS;
    if (total > out_size) total = out_size;
    for (int k = tid; k < total; k += NLEN) {
        int r = k / NCOLS;
        int c = k - r * NCOLS;
        out[k] = g_sampled[ssrc[r] * NCOLS + c];
    }
}

extern "C" void kernel_launch(void* const* d_in, const int* in_sizes, int n_in,
                              void* d_out, int out_size) {
    const float* frames   = (const float*)d_in[0];
    const int*   lips_idx = (const int*)d_in[1];
    float*       out      = (float*)d_out;

    k_frame<<<NBLK, FPB * 32>>>(frames, lips_idx);
    k_scan<<<1, 1024>>>();
    k_segment<<<NLEN, 512>>>();
    k_compact<<<1, NLEN>>>(out, out_size);
}

// round 6
// speedup vs baseline: 1.4441x; 1.3604x over previous
#include <cuda_runtime.h>

#define T_FRAMES 32768
#define N_LM 543
#define NLEN 512
#define NCOLS 122   // 21*2 hand + 40*2 lips
#define NHANDF 42
#define NLIPSF 80
#define FPB 8       // frames per block in k_frame (256 threads)
#define RAWS 128    // padded row stride of g_raw (floats) -> 512B aligned rows
#define NBLK (T_FRAMES / FPB)

// ---- device scratch (static; no allocations) ----
__device__ __align__(128) float g_raw[T_FRAMES * RAWS];
__device__ __align__(128) unsigned char g_keep8[NBLK];   // 1 bit per frame
__device__ __align__(128) int   g_map[T_FRAMES];
__device__ float g_lsum[NLIPSF];   // zero at entry of every kernel_launch (re-zeroed by k_scan)
__device__ int   g_lcnt[NLIPSF];
__device__ float g_lmean[NLIPSF];
__device__ int   g_S;
__device__ __align__(128) float g_sampled[NLEN * NCOLS];
__device__ int   g_rowflag[NLEN];
__device__ __align__(128) int g_ssrc[NLEN];
__device__ int   g_R;

__device__ __forceinline__ bool is_nan(float v) { return v != v; }

// ---- kernel 1: per-frame hand transform + keep bit + raw buffer + lips accum ----
// All 8 loads per thread issued up-front (single memory phase); keep gates stores only.
__global__ void k_frame(const float* __restrict__ frames, const int* __restrict__ lips_idx) {
    __shared__ int   s_lidx[40];
    __shared__ float s_lips[FPB][NLIPSF];
    __shared__ int   s_keepw[FPB];

    int tib  = threadIdx.x;
    int lane = tib & 31;
    int w    = tib >> 5;
    int t    = blockIdx.x * FPB + w;
    const float NANF = __int_as_float(0x7fc00000);

    if (tib < 40) s_lidx[tib] = lips_idx[tib];
    __syncthreads();

    const float* fb = frames + (size_t)t * (N_LM * 3);

    // ---- batched loads (all independent, issued before any consumption) ----
    float lx = NANF, ly = NANF, rx = NANF, ry = NANF;
    if (lane < 21) {
        lx = __ldg(fb + (468 + lane) * 3 + 0);
        ly = __ldg(fb + (468 + lane) * 3 + 1);
        rx = __ldg(fb + (522 + lane) * 3 + 0);
        ry = __ldg(fb + (522 + lane) * 3 + 1);
    }
    int   li0 = s_lidx[lane];
    float x0  = __ldg(fb + li0 * 3 + 0);
    float y0  = __ldg(fb + li0 * 3 + 1);
    float x1 = NANF, y1 = NANF;
    if (lane < 8) {
        int li1 = s_lidx[32 + lane];
        x1 = __ldg(fb + li1 * 3 + 0);
        y1 = __ldg(fb + li1 * 3 + 1);
    }

    // ---- hand transform + keep ----
    float a0 = is_nan(lx) ? 0.f : lx;
    float a1 = is_nan(ly) ? 0.f : (1.f - ly);
    float b0 = is_nan(rx) ? 0.f : (1.f - rx);
    float b1 = is_nan(ry) ? 0.f : (1.f - ry);
    float h0 = a0 + b0;
    float h1 = a1 + b1;
    int nz = (lane < 21) && ((h0 != 0.f) | (h1 != 0.f));  // terms non-negative => sum!=0 <=> any!=0
    unsigned bal = __ballot_sync(0xffffffffu, nz);
    int keep = (bal != 0u);
    if (lane == 0) s_keepw[w] = keep;

    // ---- stores (only kept frames are ever read back) ----
    float* row = &g_raw[t * RAWS];
    if (keep) {
        if (lane < 21) *(float2*)(row + 2 * lane) = make_float2(h0, h1);
        *(float2*)(row + NHANDF + 2 * lane) = make_float2(x0, y0);
        if (lane < 8) *(float2*)(row + NHANDF + 64 + 2 * lane) = make_float2(x1, y1);
    }

    // lips stash for block-level mean accumulation (NaN if frame not kept)
    s_lips[w][2 * lane + 0] = keep ? x0 : NANF;
    s_lips[w][2 * lane + 1] = keep ? y0 : NANF;
    if (lane < 8) {
        s_lips[w][64 + 2 * lane + 0] = keep ? x1 : NANF;
        s_lips[w][64 + 2 * lane + 1] = keep ? y1 : NANF;
    }
    __syncthreads();

    if (tib == 0) {
        unsigned m = 0;
        #pragma unroll
        for (int f = 0; f < FPB; f++) m |= (unsigned)s_keepw[f] << f;
        g_keep8[blockIdx.x] = (unsigned char)m;
    }

    // 80 threads: reduce FPB frames for one column, single global atomic pair
    if (tib < NLIPSF) {
        float s = 0.f; int c = 0;
        #pragma unroll
        for (int f = 0; f < FPB; f++) {
            float v = s_lips[f][tib];
            if (!is_nan(v)) { s += v; c++; }
        }
        if (c) {
            atomicAdd(&g_lsum[tib], s);
            atomicAdd(&g_lcnt[tib], c);
        }
    }
}

// ---- kernel 2: ballot-based compaction -> g_map + S; lips means; re-zero accumulators ----
__global__ void k_scan() {
    int tid  = threadIdx.x;   // 1024 threads = 32 warps
    int lane = tid & 31;
    int w    = tid >> 5;

    if (tid < NLIPSF) {
        int c = g_lcnt[tid];
        g_lmean[tid] = (c > 0) ? g_lsum[tid] / (float)c : 0.f;
        g_lsum[tid] = 0.f;     // restore zero-at-entry invariant for next launch
        g_lcnt[tid] = 0;
    }

    __shared__ unsigned s_ball[1024];  // [warp][k]
    __shared__ int s_cnt[32];
    __shared__ int s_off[32];

    int t0  = w * 1024;
    int cnt = 0;
    #pragma unroll
    for (int k = 0; k < 32; k++) {
        int t  = t0 + k * 32 + lane;
        int kp = (g_keep8[t >> 3] >> (t & 7)) & 1;
        unsigned b = __ballot_sync(0xffffffffu, kp);
        if (lane == 0) s_ball[w * 32 + k] = b;
        cnt += __popc(b);
    }
    if (lane == 0) s_cnt[w] = cnt;
    __syncthreads();
    if (tid == 0) {
        int acc = 0;
        #pragma unroll
        for (int i = 0; i < 32; i++) { s_off[i] = acc; acc += s_cnt[i]; }
        g_S = acc;
    }
    __syncthreads();

    int off = s_off[w];
    #pragma unroll
    for (int k = 0; k < 32; k++) {
        unsigned b = s_ball[w * 32 + k];
        int t = t0 + k * 32 + lane;
        if ((b >> lane) & 1)
            g_map[off + __popc(b & ((1u << lane) - 1u))] = t;
        off += __popc(b);
    }
}

// ---- kernel 3: segment means (512 blocks x 512 thr = 128 cols x 4 slices) ----
__global__ void k_segment() {
    int i = blockIdx.x;
    int S = g_S;
    int lo = 0, hi = 0;
    if (S >= 2) {
        long sm1 = (long)(S - 1);
        lo = (int)(((long)i       * sm1) >> 9);   // floor(i*(S-1)/512)
        hi = (int)(((long)(i + 1) * sm1) >> 9);
    }
    int cnt = hi - lo;   // <= 64

    __shared__ int   s_map[66];
    __shared__ float red[4][128];

    if (threadIdx.x < cnt) s_map[threadIdx.x] = g_map[lo + threadIdx.x];
    __syncthreads();

    int j     = threadIdx.x & 127;
    int slice = threadIdx.x >> 7;

    float sum = 0.f;
    if (j < NCOLS) {
        float fill = (j >= NHANDF) ? g_lmean[j - NHANDF] : 0.f;
        #pragma unroll 4
        for (int s = slice; s < cnt; s += 4) {
            int t = s_map[s];
            float v = g_raw[t * RAWS + j];
            sum += is_nan(v) ? fill : v;
        }
    }
    red[slice][j] = sum;
    __syncthreads();

    float mean = 0.f;
    if (slice == 0) {
        float total = red[0][j] + red[1][j] + red[2][j] + red[3][j];
        if (j < NCOLS) {
            mean = cnt ? total / (float)cnt : 0.f;
            g_sampled[i * NCOLS + j] = mean;
        }
    }
    __syncthreads();
    if (slice == 0) red[0][j] = mean;
    __syncthreads();
    if (threadIdx.x < 32) {
        float r = red[0][threadIdx.x] + red[0][threadIdx.x + 32]
                + red[0][threadIdx.x + 64] + red[0][threadIdx.x + 96];
        #pragma unroll
        for (int off = 16; off; off >>= 1)
            r += __shfl_xor_sync(0xffffffffu, r, off);
        if (threadIdx.x == 0) g_rowflag[i] = (r != 0.f);
    }
}

// ---- kernel 4a: ballot scan of 512 row flags -> g_ssrc + g_R (1 block, fast) ----
__global__ void k_rowscan() {
    int tid  = threadIdx.x;   // 512 threads = 16 warps
    int lane = tid & 31;
    int w    = tid >> 5;

    __shared__ int s_cnt[16];
    __shared__ int s_off[16];

    int f = g_rowflag[tid];
    unsigned b = __ballot_sync(0xffffffffu, f);
    if (lane == 0) s_cnt[w] = __popc(b);
    __syncthreads();
    if (tid == 0) {
        int acc = 0;
        #pragma unroll
        for (int i = 0; i < 16; i++) { s_off[i] = acc; acc += s_cnt[i]; }
        g_R = acc;
    }
    __syncthreads();
    if (f) g_ssrc[s_off[w] + __popc(b & ((1u << lane) - 1u))] = tid;
}

// ---- kernel 4b: parallel row copy into d_out (block r -> output row r) ----
__global__ void k_copy(float* __restrict__ out, int out_size) {
    int r = blockIdx.x;
    if (r >= g_R) return;
    int j = threadIdx.x;   // 128 threads, 122 used
    if (j < NCOLS) {
        int k = r * NCOLS + j;
        if (k < out_size)
            out[k] = g_sampled[g_ssrc[r] * NCOLS + j];
    }
}

extern "C" void kernel_launch(void* const* d_in, const int* in_sizes, int n_in,
                              void* d_out, int out_size) {
    const float* frames   = (const float*)d_in[0];
    const int*   lips_idx = (const int*)d_in[1];
    float*       out      = (float*)d_out;

    k_frame<<<NBLK, FPB * 32>>>(frames, lips_idx);
    k_scan<<<1, 1024>>>();
    k_segment<<<NLEN, 512>>>();
    k_rowscan<<<1, NLEN>>>();
    k_copy<<<NLEN, 128>>>(out, out_size);
}